// round 1
// baseline (speedup 1.0000x reference)
#include <cuda_runtime.h>

#define WDIM  64
#define SDIM  512
#define C8    64
#define XST   516   // Xs row stride (pad 4 -> conflict-free mma frag loads)
#define FGST  132   // F|G buffer stride
#define AST   68    // ATT / AXc stride

__device__ float g_inv_sigma;

__device__ __forceinline__ unsigned f2tf(float f) {
    unsigned r;
    asm("cvt.rna.tf32.f32 %0, %1;" : "=r"(r) : "f"(f));
    return r;
}

__device__ __forceinline__ void mma_tf32(float* c,
                                         unsigned a0, unsigned a1, unsigned a2, unsigned a3,
                                         unsigned b0, unsigned b1) {
    asm volatile(
        "mma.sync.aligned.m16n8k8.row.col.f32.tf32.tf32.f32 "
        "{%0,%1,%2,%3}, {%4,%5,%6,%7}, {%8,%9}, {%0,%1,%2,%3};\n"
        : "+f"(c[0]), "+f"(c[1]), "+f"(c[2]), "+f"(c[3])
        : "r"(a0), "r"(a1), "r"(a2), "r"(a3), "r"(b0), "r"(b1));
}

// ---------------------------------------------------------------------------
// Spectral-norm sigma (one tiny CTA). sigma = ||t||^2/(||t||+1e-12),
// t = normalize(W @ u) @ W  (matches reference power-iteration exactly).
// ---------------------------------------------------------------------------
__global__ void sigma_kernel(const float* __restrict__ wsn,
                             const float* __restrict__ usn) {
    __shared__ float vraw[512];
    __shared__ float red[16];
    int tid = threadIdx.x;

    // v_raw[i] = dot(W[i,:], u)
    float s0 = 0.f, s1 = 0.f, s2 = 0.f, s3 = 0.f;
    const float* wr = wsn + (size_t)tid * SDIM;
    for (int k = 0; k < SDIM; k += 4) {
        s0 += wr[k + 0] * usn[k + 0];
        s1 += wr[k + 1] * usn[k + 1];
        s2 += wr[k + 2] * usn[k + 2];
        s3 += wr[k + 3] * usn[k + 3];
    }
    float s = (s0 + s1) + (s2 + s3);
    vraw[tid] = s;

    float q = s * s;
    #pragma unroll
    for (int o = 16; o; o >>= 1) q += __shfl_xor_sync(0xffffffffu, q, o);
    if ((tid & 31) == 0) red[tid >> 5] = q;
    __syncthreads();
    if (tid == 0) {
        float z = 0.f;
        for (int i = 0; i < 16; i++) z += red[i];
        red[0] = z;
    }
    __syncthreads();
    float inv_nv = 1.f / (sqrtf(red[0]) + 1e-12f);
    __syncthreads();

    // t[j] = sum_i v[i] * W[i][j]
    float t0 = 0.f, t1 = 0.f, t2 = 0.f, t3 = 0.f;
    for (int i = 0; i < SDIM; i += 4) {
        t0 += vraw[i + 0] * wsn[(size_t)(i + 0) * SDIM + tid];
        t1 += vraw[i + 1] * wsn[(size_t)(i + 1) * SDIM + tid];
        t2 += vraw[i + 2] * wsn[(size_t)(i + 2) * SDIM + tid];
        t3 += vraw[i + 3] * wsn[(size_t)(i + 3) * SDIM + tid];
    }
    float tj = ((t0 + t1) + (t2 + t3)) * inv_nv;

    float q2 = tj * tj;
    #pragma unroll
    for (int o = 16; o; o >>= 1) q2 += __shfl_xor_sync(0xffffffffu, q2, o);
    if ((tid & 31) == 0) red[tid >> 5] = q2;
    __syncthreads();
    if (tid == 0) {
        float z = 0.f;
        for (int i = 0; i < 16; i++) z += red[i];
        float nt = sqrtf(z);
        float sigma = z / (nt + 1e-12f);
        g_inv_sigma = 1.f / sigma;
    }
}

// ---------------------------------------------------------------------------
// Fused per-(b,h) kernel. One CTA per group, 512 threads (16 warps).
// ---------------------------------------------------------------------------
extern __shared__ float smf[];

__global__ __launch_bounds__(512, 1)
void fused_kernel(const float* __restrict__ x,
                  const float* __restrict__ wf, const float* __restrict__ bf,
                  const float* __restrict__ wg, const float* __restrict__ bg,
                  const float* __restrict__ wh, const float* __restrict__ bh,
                  const float* __restrict__ gamma,
                  const float* __restrict__ ln1g, const float* __restrict__ ln1b,
                  const float* __restrict__ wsn,
                  const float* __restrict__ ln2g, const float* __restrict__ ln2b,
                  float* __restrict__ out) {
    float* Xs     = smf;                   // 64 x 516
    float* FGs    = Xs + 64 * XST;         // 64 x 132  (F cols 0..63, G cols 64..127)
    float* ATTs   = FGs + 64 * FGST;       // 64 x 68
    float* AXs    = ATTs + 64 * AST;       // 64 x 68
    float* rowsum = AXs + 64 * AST;        // 64
    float* stats  = rowsum + 64;           // 128 (mean,rstd per row)

    const int tid  = threadIdx.x;
    const int wid  = tid >> 5;
    const int lane = tid & 31;
    const int g    = lane >> 2;            // groupID
    const int t    = lane & 3;             // threadID_in_group
    const size_t base = (size_t)blockIdx.x * (WDIM * SDIM);

    // ---- load X (coalesced float4) ----
    for (int i = tid; i < WDIM * SDIM / 4; i += 512) {
        float4 v = ((const float4*)(x + base))[i];
        int r = i >> 7;
        int c = (i & 127) * 4;
        float* p = &Xs[r * XST + c];
        p[0] = v.x; p[1] = v.y; p[2] = v.z; p[3] = v.w;
    }
    __syncthreads();

    // ---- GEMM1: [F|G] = X @ [Wf|Wg] + [bf|bg]   (M=64, N=128, K=512) ----
    {
        const float* Wsel = (wid < 8) ? wf : wg;
        const float* bsel = (wid < 8) ? bf : bg;
        const int ncol = (wid & 7) * 8;     // column in Wsel
        const int cb   = wid * 8;           // column in FGs
        float acc[4][4];
        #pragma unroll
        for (int mi = 0; mi < 4; mi++)
            #pragma unroll
            for (int c = 0; c < 4; c++) acc[mi][c] = 0.f;

        for (int k = 0; k < SDIM; k += 8) {
            unsigned b0 = f2tf(Wsel[(k + t) * C8 + ncol + g]);
            unsigned b1 = f2tf(Wsel[(k + t + 4) * C8 + ncol + g]);
            #pragma unroll
            for (int mi = 0; mi < 4; mi++) {
                int r = mi * 16 + g;
                unsigned a0 = f2tf(Xs[r * XST + k + t]);
                unsigned a1 = f2tf(Xs[(r + 8) * XST + k + t]);
                unsigned a2 = f2tf(Xs[r * XST + k + t + 4]);
                unsigned a3 = f2tf(Xs[(r + 8) * XST + k + t + 4]);
                mma_tf32(acc[mi], a0, a1, a2, a3, b0, b1);
            }
        }
        float bias0 = bsel[ncol + 2 * t];
        float bias1 = bsel[ncol + 2 * t + 1];
        #pragma unroll
        for (int mi = 0; mi < 4; mi++) {
            int r = mi * 16 + g;
            FGs[r * FGST + cb + 2 * t]           = acc[mi][0] + bias0;
            FGs[r * FGST + cb + 2 * t + 1]       = acc[mi][1] + bias1;
            FGs[(r + 8) * FGST + cb + 2 * t]     = acc[mi][2] + bias0;
            FGs[(r + 8) * FGST + cb + 2 * t + 1] = acc[mi][3] + bias1;
        }
    }
    __syncthreads();

    const int mhalf = wid >> 3;            // 0/1 -> rows 0..31 / 32..63
    const int n8    = (wid & 7) * 8;

    // ---- GEMM2: ATT = sigmoid(F @ G^T)   (M=64, N=64, K=64) ----
    {
        float acc[2][4];
        #pragma unroll
        for (int mi = 0; mi < 2; mi++)
            #pragma unroll
            for (int c = 0; c < 4; c++) acc[mi][c] = 0.f;

        #pragma unroll
        for (int k = 0; k < 64; k += 8) {
            unsigned b0 = f2tf(FGs[(n8 + g) * FGST + 64 + k + t]);
            unsigned b1 = f2tf(FGs[(n8 + g) * FGST + 64 + k + t + 4]);
            #pragma unroll
            for (int mi = 0; mi < 2; mi++) {
                int r = (mhalf * 2 + mi) * 16 + g;
                unsigned a0 = f2tf(FGs[r * FGST + k + t]);
                unsigned a1 = f2tf(FGs[(r + 8) * FGST + k + t]);
                unsigned a2 = f2tf(FGs[r * FGST + k + t + 4]);
                unsigned a3 = f2tf(FGs[(r + 8) * FGST + k + t + 4]);
                mma_tf32(acc[mi], a0, a1, a2, a3, b0, b1);
            }
        }
        #pragma unroll
        for (int mi = 0; mi < 2; mi++) {
            int r = (mhalf * 2 + mi) * 16 + g;
            ATTs[r * AST + n8 + 2 * t]           = 1.f / (1.f + __expf(-acc[mi][0]));
            ATTs[r * AST + n8 + 2 * t + 1]       = 1.f / (1.f + __expf(-acc[mi][1]));
            ATTs[(r + 8) * AST + n8 + 2 * t]     = 1.f / (1.f + __expf(-acc[mi][2]));
            ATTs[(r + 8) * AST + n8 + 2 * t + 1] = 1.f / (1.f + __expf(-acc[mi][3]));
        }
    }
    __syncthreads();

    if (tid < 64) {
        float s = 0.f;
        for (int v = 0; v < 64; v++) s += ATTs[tid * AST + v];
        rowsum[tid] = s;
    }

    // ---- GEMM3+4 fused over K-chunks: ATTN = (ATT @ X) @ Wh ----
    const int ncolw = wid * 32;            // this warp's 32 output columns
    float acc[4][4][4];
    #pragma unroll
    for (int mi = 0; mi < 4; mi++)
        #pragma unroll
        for (int nj = 0; nj < 4; nj++)
            #pragma unroll
            for (int c = 0; c < 4; c++) acc[mi][nj][c] = 0.f;

    for (int kc = 0; kc < 8; kc++) {
        const int cb = kc * 64;
        // GEMM3: AXc = ATT @ X[:, cb:cb+64]  (into registers)
        float axc[2][4];
        #pragma unroll
        for (int mi = 0; mi < 2; mi++)
            #pragma unroll
            for (int c = 0; c < 4; c++) axc[mi][c] = 0.f;

        #pragma unroll
        for (int k = 0; k < 64; k += 8) {
            unsigned b0 = f2tf(Xs[(k + t) * XST + cb + n8 + g]);
            unsigned b1 = f2tf(Xs[(k + t + 4) * XST + cb + n8 + g]);
            #pragma unroll
            for (int mi = 0; mi < 2; mi++) {
                int r = (mhalf * 2 + mi) * 16 + g;
                unsigned a0 = f2tf(ATTs[r * AST + k + t]);
                unsigned a1 = f2tf(ATTs[(r + 8) * AST + k + t]);
                unsigned a2 = f2tf(ATTs[r * AST + k + t + 4]);
                unsigned a3 = f2tf(ATTs[(r + 8) * AST + k + t + 4]);
                mma_tf32(axc[mi], a0, a1, a2, a3, b0, b1);
            }
        }
        __syncthreads();   // previous chunk's GEMM4 done reading AXs
        #pragma unroll
        for (int mi = 0; mi < 2; mi++) {
            int r = (mhalf * 2 + mi) * 16 + g;
            AXs[r * AST + n8 + 2 * t]           = axc[mi][0];
            AXs[r * AST + n8 + 2 * t + 1]       = axc[mi][1];
            AXs[(r + 8) * AST + n8 + 2 * t]     = axc[mi][2];
            AXs[(r + 8) * AST + n8 + 2 * t + 1] = axc[mi][3];
        }
        __syncthreads();

        // GEMM4 partial: acc += AXc @ Wh[cb:cb+64, ncolw:ncolw+32]
        const float* whp = wh + (size_t)cb * SDIM;
        #pragma unroll 2
        for (int k = 0; k < 64; k += 8) {
            unsigned bf0[4], bf1[4];
            #pragma unroll
            for (int nj = 0; nj < 4; nj++) {
                bf0[nj] = f2tf(whp[(k + t) * SDIM + ncolw + nj * 8 + g]);
                bf1[nj] = f2tf(whp[(k + t + 4) * SDIM + ncolw + nj * 8 + g]);
            }
            #pragma unroll
            for (int mi = 0; mi < 4; mi++) {
                int r = mi * 16 + g;
                unsigned a0 = f2tf(AXs[r * AST + k + t]);
                unsigned a1 = f2tf(AXs[(r + 8) * AST + k + t]);
                unsigned a2 = f2tf(AXs[r * AST + k + t + 4]);
                unsigned a3 = f2tf(AXs[(r + 8) * AST + k + t + 4]);
                #pragma unroll
                for (int nj = 0; nj < 4; nj++)
                    mma_tf32(acc[mi][nj], a0, a1, a2, a3, bf0[nj], bf1[nj]);
            }
        }
    }

    // ---- epilogue 1: t = gamma*(attn + rowsum*bh) + x  -> overwrite Xs ----
    {
        float gam = gamma[0];
        #pragma unroll
        for (int mi = 0; mi < 4; mi++) {
            #pragma unroll
            for (int nj = 0; nj < 4; nj++) {
                int r0 = mi * 16 + g, r1 = r0 + 8;
                int c0 = ncolw + nj * 8 + 2 * t, c1 = c0 + 1;
                float bh0 = bh[c0], bh1 = bh[c1];
                float rs0 = rowsum[r0], rs1 = rowsum[r1];
                Xs[r0 * XST + c0] += gam * (acc[mi][nj][0] + rs0 * bh0);
                Xs[r0 * XST + c1] += gam * (acc[mi][nj][1] + rs0 * bh1);
                Xs[r1 * XST + c0] += gam * (acc[mi][nj][2] + rs1 * bh0);
                Xs[r1 * XST + c1] += gam * (acc[mi][nj][3] + rs1 * bh1);
            }
        }
    }
    __syncthreads();

    // ---- LN1 (rows of 512), result back into Xs ----
    {
        int row = tid >> 3, j0 = tid & 7;
        float s = 0.f, sq = 0.f;
        for (int c = j0; c < SDIM; c += 8) {
            float v = Xs[row * XST + c];
            s += v; sq += v * v;
        }
        #pragma unroll
        for (int o = 1; o <= 4; o <<= 1) {
            s  += __shfl_xor_sync(0xffffffffu, s, o);
            sq += __shfl_xor_sync(0xffffffffu, sq, o);
        }
        if (j0 == 0) {
            float mean = s * (1.f / SDIM);
            float var  = sq * (1.f / SDIM) - mean * mean;
            stats[row * 2]     = mean;
            stats[row * 2 + 1] = rsqrtf(var + 1e-6f);
        }
    }
    __syncthreads();
    for (int idx = tid; idx < WDIM * SDIM; idx += 512) {
        int r = idx >> 9, c = idx & (SDIM - 1);
        float v = (Xs[r * XST + c] - stats[r * 2]) * stats[r * 2 + 1];
        Xs[r * XST + c] = v * ln1g[c] + ln1b[c];
    }
    __syncthreads();

    // ---- GEMM5: Y = out1 @ Wsn  (scaled by 1/sigma at epilogue) ----
    #pragma unroll
    for (int mi = 0; mi < 4; mi++)
        #pragma unroll
        for (int nj = 0; nj < 4; nj++)
            #pragma unroll
            for (int c = 0; c < 4; c++) acc[mi][nj][c] = 0.f;

    #pragma unroll 2
    for (int k = 0; k < SDIM; k += 8) {
        unsigned bf0[4], bf1[4];
        #pragma unroll
        for (int nj = 0; nj < 4; nj++) {
            bf0[nj] = f2tf(wsn[(size_t)(k + t) * SDIM + ncolw + nj * 8 + g]);
            bf1[nj] = f2tf(wsn[(size_t)(k + t + 4) * SDIM + ncolw + nj * 8 + g]);
        }
        #pragma unroll
        for (int mi = 0; mi < 4; mi++) {
            int r = mi * 16 + g;
            unsigned a0 = f2tf(Xs[r * XST + k + t]);
            unsigned a1 = f2tf(Xs[(r + 8) * XST + k + t]);
            unsigned a2 = f2tf(Xs[r * XST + k + t + 4]);
            unsigned a3 = f2tf(Xs[(r + 8) * XST + k + t + 4]);
            #pragma unroll
            for (int nj = 0; nj < 4; nj++)
                mma_tf32(acc[mi][nj], a0, a1, a2, a3, bf0[nj], bf1[nj]);
        }
    }
    __syncthreads();   // all warps done reading Xs before overwrite

    // ---- epilogue 2: y = relu(acc / sigma) -> Xs ----
    {
        float invsig = g_inv_sigma;
        #pragma unroll
        for (int mi = 0; mi < 4; mi++) {
            #pragma unroll
            for (int nj = 0; nj < 4; nj++) {
                int r0 = mi * 16 + g, r1 = r0 + 8;
                int c0 = ncolw + nj * 8 + 2 * t, c1 = c0 + 1;
                Xs[r0 * XST + c0] = fmaxf(acc[mi][nj][0] * invsig, 0.f);
                Xs[r0 * XST + c1] = fmaxf(acc[mi][nj][1] * invsig, 0.f);
                Xs[r1 * XST + c0] = fmaxf(acc[mi][nj][2] * invsig, 0.f);
                Xs[r1 * XST + c1] = fmaxf(acc[mi][nj][3] * invsig, 0.f);
            }
        }
    }
    __syncthreads();

    // ---- LN2 -> global out ----
    {
        int row = tid >> 3, j0 = tid & 7;
        float s = 0.f, sq = 0.f;
        for (int c = j0; c < SDIM; c += 8) {
            float v = Xs[row * XST + c];
            s += v; sq += v * v;
        }
        #pragma unroll
        for (int o = 1; o <= 4; o <<= 1) {
            s  += __shfl_xor_sync(0xffffffffu, s, o);
            sq += __shfl_xor_sync(0xffffffffu, sq, o);
        }
        if (j0 == 0) {
            float mean = s * (1.f / SDIM);
            float var  = sq * (1.f / SDIM) - mean * mean;
            stats[row * 2]     = mean;
            stats[row * 2 + 1] = rsqrtf(var + 1e-6f);
        }
    }
    __syncthreads();
    for (int idx = tid; idx < WDIM * SDIM; idx += 512) {
        int r = idx >> 9, c = idx & (SDIM - 1);
        float v = (Xs[r * XST + c] - stats[r * 2]) * stats[r * 2 + 1];
        out[base + idx] = v * ln2g[c] + ln2b[c];
    }
}

// ---------------------------------------------------------------------------
extern "C" void kernel_launch(void* const* d_in, const int* in_sizes, int n_in,
                              void* d_out, int out_size) {
    (void)in_sizes; (void)n_in; (void)out_size;
    const float* x    = (const float*)d_in[0];
    const float* wf   = (const float*)d_in[1];
    const float* bf   = (const float*)d_in[2];
    const float* wg   = (const float*)d_in[3];
    const float* bg   = (const float*)d_in[4];
    const float* wh   = (const float*)d_in[5];
    const float* bh   = (const float*)d_in[6];
    const float* gam  = (const float*)d_in[7];
    const float* ln1g = (const float*)d_in[8];
    const float* ln1b = (const float*)d_in[9];
    const float* wsn  = (const float*)d_in[10];
    const float* usn  = (const float*)d_in[11];
    const float* ln2g = (const float*)d_in[12];
    const float* ln2b = (const float*)d_in[13];
    float* out = (float*)d_out;

    sigma_kernel<<<1, 512>>>(wsn, usn);

    const int smem_bytes = (64 * XST + 64 * FGST + 64 * AST + 64 * AST + 64 + 128) * 4;
    cudaFuncSetAttribute(fused_kernel, cudaFuncAttributeMaxDynamicSharedMemorySize, smem_bytes);
    fused_kernel<<<1024, 512, smem_bytes>>>(x, wf, bf, wg, bg, wh, bh, gam,
                                            ln1g, ln1b, wsn, ln2g, ln2b, out);
}

// round 2
// speedup vs baseline: 1.4382x; 1.4382x over previous
#include <cuda_runtime.h>

#define WDIM  64
#define SDIM  512
#define C8    64
#define XST   516   // Xs row stride
#define FGST  132
#define AST   68

__device__ float g_inv_sigma;
// fragment-packed, tf32-pre-rounded weight copies
__device__ float g_whP [262144];  // wh  [512x512]
__device__ float g_wsnP[262144];  // wsn [512x512]
__device__ float g_fgP [65536];   // [wf|wg] packed

__device__ __forceinline__ unsigned f2tf(float f) {
    unsigned r;
    asm("cvt.rna.tf32.f32 %0, %1;" : "=r"(r) : "f"(f));
    return r;
}
__device__ __forceinline__ float rndtf(float f) { return __uint_as_float(f2tf(f)); }
__device__ __forceinline__ unsigned bits(float f) { return __float_as_uint(f); }

__device__ __forceinline__ void mma_tf32(float* c,
                                         unsigned a0, unsigned a1, unsigned a2, unsigned a3,
                                         unsigned b0, unsigned b1) {
    asm volatile(
        "mma.sync.aligned.m16n8k8.row.col.f32.tf32.tf32.f32 "
        "{%0,%1,%2,%3}, {%4,%5,%6,%7}, {%8,%9}, {%0,%1,%2,%3};\n"
        : "+f"(c[0]), "+f"(c[1]), "+f"(c[2]), "+f"(c[3])
        : "r"(a0), "r"(a1), "r"(a2), "r"(a3), "r"(b0), "r"(b1));
}

// ---------------------------------------------------------------------------
// init kernel: blocks 0..511 pack+round weights; block 512 computes sigma.
// whP/wsnP layout: idx = ((((ks*8+ng)*2+r)*2+h)*32+l)*4+j
//   element = W[ks*8 + (l&3) + r*4][ng*64 + (h*4+j)*8 + (l>>2)]
// fgP layout: idx = (((ks*4+ng)*2+r)*32+l)*4+j
//   col = ng*32 + j*8 + (l>>2); row = ks*8 + (l&3) + r*4;  col<64 -> wf else wg
// ---------------------------------------------------------------------------
__global__ __launch_bounds__(512)
void init_kernel(const float* __restrict__ wf, const float* __restrict__ wg,
                 const float* __restrict__ wh, const float* __restrict__ wsn,
                 const float* __restrict__ usn) {
    if (blockIdx.x < 512) {
        int i = blockIdx.x * 512 + threadIdx.x;   // 0..262143
        {
            int j = i & 3, l = (i >> 2) & 31, h = (i >> 7) & 1, r = (i >> 8) & 1;
            int ng = (i >> 9) & 7, ks = i >> 12;
            int row = ks * 8 + (l & 3) + r * 4;
            int col = ng * 64 + (h * 4 + j) * 8 + (l >> 2);
            g_whP[i]  = rndtf(wh [(size_t)row * SDIM + col]);
            g_wsnP[i] = rndtf(wsn[(size_t)row * SDIM + col]);
        }
        if (i < 65536) {
            int j = i & 3, l = (i >> 2) & 31, r = (i >> 7) & 1;
            int ng = (i >> 8) & 3, ks = i >> 10;
            int row = ks * 8 + (l & 3) + r * 4;
            int col = ng * 32 + j * 8 + (l >> 2);
            g_fgP[i] = rndtf(col < 64 ? wf[(size_t)row * C8 + col]
                                      : wg[(size_t)row * C8 + col - 64]);
        }
        return;
    }
    // ---- sigma (one block) ----
    __shared__ float us[512];
    __shared__ float vs[512];
    __shared__ float red[17];
    int tid = threadIdx.x, wid = tid >> 5, lane = tid & 31;
    us[tid] = usn[tid];
    __syncthreads();

    // v = W @ u, coalesced: each warp handles 32 rows
    float q = 0.f;
    for (int rr = 0; rr < 32; rr++) {
        int row = wid * 32 + rr;
        const float4* wr = (const float4*)(wsn + (size_t)row * SDIM);
        const float4* ur = (const float4*)us;
        float s = 0.f;
        #pragma unroll
        for (int i = 0; i < 4; i++) {
            float4 w = wr[lane + i * 32], u = ur[lane + i * 32];
            s += w.x * u.x + w.y * u.y + w.z * u.z + w.w * u.w;
        }
        #pragma unroll
        for (int o = 16; o; o >>= 1) s += __shfl_xor_sync(0xffffffffu, s, o);
        if (lane == 0) { vs[row] = s; q += s * s; }
    }
    if (lane == 0) red[wid] = q;
    __syncthreads();
    if (tid == 0) {
        float z = 0.f;
        for (int i = 0; i < 16; i++) z += red[i];
        red[16] = 1.f / (sqrtf(z) + 1e-12f);
    }
    __syncthreads();
    float inv_nv = red[16];
    __syncthreads();

    // t = v @ W (coalesced across threads)
    float t0 = 0.f, t1 = 0.f, t2 = 0.f, t3 = 0.f;
    for (int i = 0; i < SDIM; i += 4) {
        t0 += vs[i + 0] * wsn[(size_t)(i + 0) * SDIM + tid];
        t1 += vs[i + 1] * wsn[(size_t)(i + 1) * SDIM + tid];
        t2 += vs[i + 2] * wsn[(size_t)(i + 2) * SDIM + tid];
        t3 += vs[i + 3] * wsn[(size_t)(i + 3) * SDIM + tid];
    }
    float tj = ((t0 + t1) + (t2 + t3)) * inv_nv;
    float q2 = tj * tj;
    #pragma unroll
    for (int o = 16; o; o >>= 1) q2 += __shfl_xor_sync(0xffffffffu, q2, o);
    if (lane == 0) red[wid] = q2;
    __syncthreads();
    if (tid == 0) {
        float z = 0.f;
        for (int i = 0; i < 16; i++) z += red[i];
        float nt = sqrtf(z);
        g_inv_sigma = (nt + 1e-12f) / z;   // 1/sigma, sigma = z/(nt+eps)
    }
}

// ---------------------------------------------------------------------------
// Shared inner block for GEMM4 / GEMM5: acc[2][8][4] += A(64xK) @ Wpacked
// ---------------------------------------------------------------------------
template <int STRIDE>
__device__ __forceinline__ void mma_block(float (&acc)[2][8][4],
                                          const float* __restrict__ A,
                                          const float* __restrict__ WP,
                                          int ksw0, int nks,
                                          int ng, int mg, int g, int t, int lane) {
    #pragma unroll 2
    for (int ks = 0; ks < nks; ks++) {
        int ksG = ksw0 + ks;
        const uint4* wp = reinterpret_cast<const uint4*>(WP)
                        + (size_t)((ksG * 8 + ng) * 4) * 32 + lane;
        uint4 Bv0 = wp[0];          // r=0, nj 0..3
        uint4 Bv1 = wp[32];         // r=0, nj 4..7
        uint4 Bv2 = wp[64];         // r=1, nj 0..3
        uint4 Bv3 = wp[96];         // r=1, nj 4..7
        unsigned b0[8] = {Bv0.x, Bv0.y, Bv0.z, Bv0.w, Bv1.x, Bv1.y, Bv1.z, Bv1.w};
        unsigned b1[8] = {Bv2.x, Bv2.y, Bv2.z, Bv2.w, Bv3.x, Bv3.y, Bv3.z, Bv3.w};
        int k = ks * 8;
        #pragma unroll
        for (int mi = 0; mi < 2; mi++) {
            int r = mg * 32 + mi * 16 + g;
            unsigned a0 = bits(A[r * STRIDE + k + t]);
            unsigned a1 = bits(A[(r + 8) * STRIDE + k + t]);
            unsigned a2 = bits(A[r * STRIDE + k + t + 4]);
            unsigned a3 = bits(A[(r + 8) * STRIDE + k + t + 4]);
            #pragma unroll
            for (int nj = 0; nj < 8; nj++)
                mma_tf32(acc[mi][nj], a0, a1, a2, a3, b0[nj], b1[nj]);
        }
    }
}

// ---------------------------------------------------------------------------
extern __shared__ float smf[];

__global__ __launch_bounds__(512, 1)
void fused_kernel(const float* __restrict__ x,
                  const float* __restrict__ bf, const float* __restrict__ bg,
                  const float* __restrict__ bh,
                  const float* __restrict__ gamma,
                  const float* __restrict__ ln1g, const float* __restrict__ ln1b,
                  const float* __restrict__ ln2g, const float* __restrict__ ln2b,
                  float* __restrict__ out) {
    float* Xs     = smf;                    // 64 x 516
    float* FGs    = Xs + 64 * XST;          // 64 x 132
    float* ATTs   = FGs + 64 * FGST;        // 64 x 68
    float* AXs    = ATTs + 64 * AST;        // 2 x (64 x 68)
    float* rowsum = AXs + 2 * 64 * AST;     // 64
    float* stats  = rowsum + 64;            // 128

    const int tid  = threadIdx.x;
    const int wid  = tid >> 5;
    const int lane = tid & 31;
    const int g    = lane >> 2;
    const int t    = lane & 3;
    const size_t base = (size_t)blockIdx.x * (WDIM * SDIM);

    // ---- load X, pre-rounded to tf32 ----
    for (int i = tid; i < WDIM * SDIM / 4; i += 512) {
        float4 v = ((const float4*)(x + base))[i];
        int r = i >> 7;
        int c = (i & 127) * 4;
        float* p = &Xs[r * XST + c];
        p[0] = rndtf(v.x); p[1] = rndtf(v.y); p[2] = rndtf(v.z); p[3] = rndtf(v.w);
    }
    __syncthreads();

    // ---- GEMM1: [F|G] = X @ [Wf|Wg] + bias   (4m x 4n warp tiling) ----
    {
        const int mg1 = wid & 3;            // rows mg1*16 + g, +8
        const int ng1 = wid >> 2;           // cols ng1*32
        float acc1[4][4];
        #pragma unroll
        for (int nj = 0; nj < 4; nj++)
            #pragma unroll
            for (int c = 0; c < 4; c++) acc1[nj][c] = 0.f;

        const int rA = mg1 * 16 + g;
        #pragma unroll 2
        for (int ks = 0; ks < 64; ks++) {
            const uint4* fp = reinterpret_cast<const uint4*>(g_fgP)
                            + (size_t)((ks * 4 + ng1) * 2) * 32 + lane;
            uint4 B0 = fp[0];
            uint4 B1 = fp[32];
            unsigned b0[4] = {B0.x, B0.y, B0.z, B0.w};
            unsigned b1[4] = {B1.x, B1.y, B1.z, B1.w};
            int k = ks * 8;
            unsigned a0 = bits(Xs[rA * XST + k + t]);
            unsigned a1 = bits(Xs[(rA + 8) * XST + k + t]);
            unsigned a2 = bits(Xs[rA * XST + k + t + 4]);
            unsigned a3 = bits(Xs[(rA + 8) * XST + k + t + 4]);
            #pragma unroll
            for (int nj = 0; nj < 4; nj++)
                mma_tf32(acc1[nj], a0, a1, a2, a3, b0[nj], b1[nj]);
        }
        #pragma unroll
        for (int nj = 0; nj < 4; nj++) {
            int cg = ng1 * 32 + nj * 8 + 2 * t;
            float bias0 = (cg < 64) ? bf[cg] : bg[cg - 64];
            float bias1 = (cg + 1 < 64) ? bf[cg + 1] : bg[cg + 1 - 64];
            FGs[rA * FGST + cg]           = rndtf(acc1[nj][0] + bias0);
            FGs[rA * FGST + cg + 1]       = rndtf(acc1[nj][1] + bias1);
            FGs[(rA + 8) * FGST + cg]     = rndtf(acc1[nj][2] + bias0);
            FGs[(rA + 8) * FGST + cg + 1] = rndtf(acc1[nj][3] + bias1);
        }
    }
    __syncthreads();

    const int mhalf = wid >> 3;
    const int n8    = (wid & 7) * 8;

    // ---- GEMM2: ATT = sigmoid(F @ G^T) ----
    {
        float acc2[2][4];
        #pragma unroll
        for (int mi = 0; mi < 2; mi++)
            #pragma unroll
            for (int c = 0; c < 4; c++) acc2[mi][c] = 0.f;

        #pragma unroll
        for (int k = 0; k < 64; k += 8) {
            unsigned b0 = bits(FGs[(n8 + g) * FGST + 64 + k + t]);
            unsigned b1 = bits(FGs[(n8 + g) * FGST + 64 + k + t + 4]);
            #pragma unroll
            for (int mi = 0; mi < 2; mi++) {
                int r = (mhalf * 2 + mi) * 16 + g;
                unsigned a0 = bits(FGs[r * FGST + k + t]);
                unsigned a1 = bits(FGs[(r + 8) * FGST + k + t]);
                unsigned a2 = bits(FGs[r * FGST + k + t + 4]);
                unsigned a3 = bits(FGs[(r + 8) * FGST + k + t + 4]);
                mma_tf32(acc2[mi], a0, a1, a2, a3, b0, b1);
            }
        }
        #pragma unroll
        for (int mi = 0; mi < 2; mi++) {
            int r = (mhalf * 2 + mi) * 16 + g;
            ATTs[r * AST + n8 + 2 * t]           = rndtf(1.f / (1.f + __expf(-acc2[mi][0])));
            ATTs[r * AST + n8 + 2 * t + 1]       = rndtf(1.f / (1.f + __expf(-acc2[mi][1])));
            ATTs[(r + 8) * AST + n8 + 2 * t]     = rndtf(1.f / (1.f + __expf(-acc2[mi][2])));
            ATTs[(r + 8) * AST + n8 + 2 * t + 1] = rndtf(1.f / (1.f + __expf(-acc2[mi][3])));
        }
    }
    __syncthreads();

    if (tid < 64) {
        float s = 0.f;
        for (int v = 0; v < 64; v++) s += ATTs[tid * AST + v];
        rowsum[tid] = s;
    }

    // ---- GEMM3+4 fused: ATTN = (ATT @ X) @ Wh ----
    const int mg = wid & 1;
    const int ng = wid >> 1;
    float acc[2][8][4];
    #pragma unroll
    for (int mi = 0; mi < 2; mi++)
        #pragma unroll
        for (int nj = 0; nj < 8; nj++)
            #pragma unroll
            for (int c = 0; c < 4; c++) acc[mi][nj][c] = 0.f;

    for (int kc = 0; kc < 8; kc++) {
        const int cb = kc * 64;
        float* AXb = AXs + (kc & 1) * 64 * AST;

        float axc[2][4];
        #pragma unroll
        for (int mi = 0; mi < 2; mi++)
            #pragma unroll
            for (int c = 0; c < 4; c++) axc[mi][c] = 0.f;

        #pragma unroll
        for (int k = 0; k < 64; k += 8) {
            unsigned b0 = bits(Xs[(k + t) * XST + cb + n8 + g]);
            unsigned b1 = bits(Xs[(k + t + 4) * XST + cb + n8 + g]);
            #pragma unroll
            for (int mi = 0; mi < 2; mi++) {
                int r = (mhalf * 2 + mi) * 16 + g;
                unsigned a0 = bits(ATTs[r * AST + k + t]);
                unsigned a1 = bits(ATTs[(r + 8) * AST + k + t]);
                unsigned a2 = bits(ATTs[r * AST + k + t + 4]);
                unsigned a3 = bits(ATTs[(r + 8) * AST + k + t + 4]);
                mma_tf32(axc[mi], a0, a1, a2, a3, b0, b1);
            }
        }
        #pragma unroll
        for (int mi = 0; mi < 2; mi++) {
            int r = (mhalf * 2 + mi) * 16 + g;
            AXb[r * AST + n8 + 2 * t]           = rndtf(axc[mi][0]);
            AXb[r * AST + n8 + 2 * t + 1]       = rndtf(axc[mi][1]);
            AXb[(r + 8) * AST + n8 + 2 * t]     = rndtf(axc[mi][2]);
            AXb[(r + 8) * AST + n8 + 2 * t + 1] = rndtf(axc[mi][3]);
        }
        __syncthreads();

        mma_block<AST>(acc, AXb, g_whP, kc * 8, 8, ng, mg, g, t, lane);
    }

    // ---- epilogue 1: Xs = gamma*(attn + rowsum*bh)  (x added in LN1 pass) ----
    {
        float gam = gamma[0];
        #pragma unroll
        for (int mi = 0; mi < 2; mi++) {
            int r0 = mg * 32 + mi * 16 + g, r1 = r0 + 8;
            float rs0 = rowsum[r0], rs1 = rowsum[r1];
            #pragma unroll
            for (int nj = 0; nj < 8; nj++) {
                int c0 = ng * 64 + nj * 8 + 2 * t;
                float bh0 = bh[c0], bh1 = bh[c0 + 1];
                Xs[r0 * XST + c0]     = gam * (acc[mi][nj][0] + rs0 * bh0);
                Xs[r0 * XST + c0 + 1] = gam * (acc[mi][nj][1] + rs0 * bh1);
                Xs[r1 * XST + c0]     = gam * (acc[mi][nj][2] + rs1 * bh0);
                Xs[r1 * XST + c0 + 1] = gam * (acc[mi][nj][3] + rs1 * bh1);
            }
        }
    }
    __syncthreads();

    // ---- LN1 pass1: add residual x (re-read), accumulate stats ----
    {
        int row = tid >> 3, j0 = tid & 7;
        const float4* xr = (const float4*)(x + base + (size_t)row * SDIM);
        float4* Xr = (float4*)(Xs + row * XST);
        float s = 0.f, sq = 0.f;
        #pragma unroll
        for (int i = 0; i < 16; i++) {
            int c4 = j0 + i * 8;
            float4 v = Xr[c4];
            float4 xv = xr[c4];
            v.x += xv.x; v.y += xv.y; v.z += xv.z; v.w += xv.w;
            Xr[c4] = v;
            s  += (v.x + v.y) + (v.z + v.w);
            sq += (v.x * v.x + v.y * v.y) + (v.z * v.z + v.w * v.w);
        }
        #pragma unroll
        for (int o = 1; o <= 4; o <<= 1) {
            s  += __shfl_xor_sync(0xffffffffu, s, o);
            sq += __shfl_xor_sync(0xffffffffu, sq, o);
        }
        if (j0 == 0) {
            float mean = s * (1.f / SDIM);
            float var  = sq * (1.f / SDIM) - mean * mean;
            stats[row * 2]     = mean;
            stats[row * 2 + 1] = rsqrtf(var + 1e-6f);
        }
    }
    __syncthreads();
    // ---- LN1 pass2: normalize, pre-round (feeds GEMM5 only) ----
    {
        int row = tid >> 3, j0 = tid & 7;
        float mean = stats[row * 2], rstd = stats[row * 2 + 1];
        float4* Xr = (float4*)(Xs + row * XST);
        #pragma unroll
        for (int i = 0; i < 16; i++) {
            int c4 = j0 + i * 8;
            float4 v = Xr[c4];
            float4 gv = ((const float4*)ln1g)[c4];
            float4 bv = ((const float4*)ln1b)[c4];
            v.x = rndtf((v.x - mean) * rstd * gv.x + bv.x);
            v.y = rndtf((v.y - mean) * rstd * gv.y + bv.y);
            v.z = rndtf((v.z - mean) * rstd * gv.z + bv.z);
            v.w = rndtf((v.w - mean) * rstd * gv.w + bv.w);
            Xr[c4] = v;
        }
    }
    __syncthreads();

    // ---- GEMM5: Y = out1 @ Wsn ----
    #pragma unroll
    for (int mi = 0; mi < 2; mi++)
        #pragma unroll
        for (int nj = 0; nj < 8; nj++)
            #pragma unroll
            for (int c = 0; c < 4; c++) acc[mi][nj][c] = 0.f;

    mma_block<XST>(acc, Xs, g_wsnP, 0, 64, ng, mg, g, t, lane);
    __syncthreads();

    // ---- epilogue 2: relu(acc/sigma) -> Xs ----
    {
        float invsig = g_inv_sigma;
        #pragma unroll
        for (int mi = 0; mi < 2; mi++) {
            int r0 = mg * 32 + mi * 16 + g, r1 = r0 + 8;
            #pragma unroll
            for (int nj = 0; nj < 8; nj++) {
                int c0 = ng * 64 + nj * 8 + 2 * t;
                Xs[r0 * XST + c0]     = fmaxf(acc[mi][nj][0] * invsig, 0.f);
                Xs[r0 * XST + c0 + 1] = fmaxf(acc[mi][nj][1] * invsig, 0.f);
                Xs[r1 * XST + c0]     = fmaxf(acc[mi][nj][2] * invsig, 0.f);
                Xs[r1 * XST + c0 + 1] = fmaxf(acc[mi][nj][3] * invsig, 0.f);
            }
        }
    }
    __syncthreads();

    // ---- LN2 pass1 ----
    {
        int row = tid >> 3, j0 = tid & 7;
        const float4* Xr = (const float4*)(Xs + row * XST);
        float s = 0.f, sq = 0.f;
        #pragma unroll
        for (int i = 0; i < 16; i++) {
            float4 v = Xr[j0 + i * 8];
            s  += (v.x + v.y) + (v.z + v.w);
            sq += (v.x * v.x + v.y * v.y) + (v.z * v.z + v.w * v.w);
        }
        #pragma unroll
        for (int o = 1; o <= 4; o <<= 1) {
            s  += __shfl_xor_sync(0xffffffffu, s, o);
            sq += __shfl_xor_sync(0xffffffffu, sq, o);
        }
        if (j0 == 0) {
            float mean = s * (1.f / SDIM);
            float var  = sq * (1.f / SDIM) - mean * mean;
            stats[row * 2]     = mean;
            stats[row * 2 + 1] = rsqrtf(var + 1e-6f);
        }
    }
    __syncthreads();
    // ---- LN2 pass2 -> global out ----
    {
        int row = tid >> 3, j0 = tid & 7;
        float mean = stats[row * 2], rstd = stats[row * 2 + 1];
        const float4* Xr = (const float4*)(Xs + row * XST);
        float4* orow = (float4*)(out + base + (size_t)row * SDIM);
        #pragma unroll
        for (int i = 0; i < 16; i++) {
            int c4 = j0 + i * 8;
            float4 v = Xr[c4];
            float4 gv = ((const float4*)ln2g)[c4];
            float4 bv = ((const float4*)ln2b)[c4];
            v.x = (v.x - mean) * rstd * gv.x + bv.x;
            v.y = (v.y - mean) * rstd * gv.y + bv.y;
            v.z = (v.z - mean) * rstd * gv.z + bv.z;
            v.w = (v.w - mean) * rstd * gv.w + bv.w;
            orow[c4] = v;
        }
    }
}

// ---------------------------------------------------------------------------
extern "C" void kernel_launch(void* const* d_in, const int* in_sizes, int n_in,
                              void* d_out, int out_size) {
    (void)in_sizes; (void)n_in; (void)out_size;
    const float* x    = (const float*)d_in[0];
    const float* wf   = (const float*)d_in[1];
    const float* bf   = (const float*)d_in[2];
    const float* wg   = (const float*)d_in[3];
    const float* bg   = (const float*)d_in[4];
    const float* wh   = (const float*)d_in[5];
    const float* bh   = (const float*)d_in[6];
    const float* gam  = (const float*)d_in[7];
    const float* ln1g = (const float*)d_in[8];
    const float* ln1b = (const float*)d_in[9];
    const float* wsn  = (const float*)d_in[10];
    const float* usn  = (const float*)d_in[11];
    const float* ln2g = (const float*)d_in[12];
    const float* ln2b = (const float*)d_in[13];
    float* out = (float*)d_out;

    init_kernel<<<513, 512>>>(wf, wg, wh, wsn, usn);

    const int smem_bytes = (64 * XST + 64 * FGST + 64 * AST + 2 * 64 * AST + 64 + 128) * 4;
    cudaFuncSetAttribute(fused_kernel, cudaFuncAttributeMaxDynamicSharedMemorySize, smem_bytes);
    fused_kernel<<<1024, 512, smem_bytes>>>(x, bf, bg, bh, gam,
                                            ln1g, ln1b, ln2g, ln2b, out);
}